// round 2
// baseline (speedup 1.0000x reference)
#include <cuda_runtime.h>
#include <math.h>

#define NMAX 10000
#define EMAX 160000
#define KT   125
#define CI1  64
#define CC   128
#define LD1  (KT*CI1 + CI1)    // 8064
#define LD2  (KT*CC + CC)      // 16128

// ---------------- scratch (device globals: no allocations allowed) ----------
__device__ __align__(16) float g_acc[(size_t)NMAX * LD2];   // 645MB, reused by conv1/conv2
__device__ __align__(16) float g_wcat[LD2 * CC];            // W ++ Wr concatenated
__device__ __align__(16) float g_wcs[CC * CC];              // shortcut weights
__device__ __align__(16) float g_out1[NMAX * CC];
__device__ __align__(16) float g_h1e [NMAX * CC];
__device__ __align__(16) float g_out2[NMAX * CC];
__device__ __align__(16) float g_outs[NMAX * CC];
__device__ __align__(16) float g_sin [NMAX * CC];           // [s_agg | x] for shortcut GEMM
__device__ float g_w8  [EMAX * 8];
__device__ int   g_idx8[EMAX * 8];
__device__ int   g_eord[EMAX];
__device__ int   g_rowptr[NMAX + 1];
__device__ int   g_cursor[NMAX];
__device__ int   g_degcnt[NMAX];
__device__ float g_red  [6 * CC];                            // 3 BNs x (sum, sumsq)
__device__ float g_scale[3 * CC];
__device__ float g_shift[3 * CC];

// ---------------- small kernels ---------------------------------------------
__global__ void k_zero(int n) {
    int i = blockIdx.x * blockDim.x + threadIdx.x;
    if (i < n) g_degcnt[i] = 0;
    if (i < 6 * CC) g_red[i] = 0.f;
}

// per-edge spline basis (degree-1 open B-spline, K=5, DIM=3) + degree count
__global__ void k_pre(const float* __restrict__ attr, const int* __restrict__ dst, int E) {
    int e = blockIdx.x * blockDim.x + threadIdx.x;
    if (e >= E) return;
    float v0 = attr[e * 3 + 0] * 4.f;
    float v1 = attr[e * 3 + 1] * 4.f;
    float v2 = attr[e * 3 + 2] * 4.f;
    float b0 = floorf(v0), b1 = floorf(v1), b2 = floorf(v2);
    float f0 = v0 - b0, f1 = v1 - b1, f2 = v2 - b2;
    int i0 = (int)b0, i1 = (int)b1, i2 = (int)b2;
#pragma unroll
    for (int m = 0; m < 8; m++) {
        int t0 = m & 1, t1 = (m >> 1) & 1, t2 = (m >> 2) & 1;
        float w = (t0 ? f0 : 1.f - f0) * (t1 ? f1 : 1.f - f1) * (t2 ? f2 : 1.f - f2);
        int c0 = min(max(i0 + t0, 0), 4);
        int c1 = min(max(i1 + t1, 0), 4);
        int c2 = min(max(i2 + t2, 0), 4);
        g_idx8[e * 8 + m] = (c0 * 5 + c1) * 5 + c2;
        g_w8[e * 8 + m] = w;
    }
    atomicAdd(&g_degcnt[dst[e]], 1);
}

// single-block exclusive scan of degcnt -> rowptr, cursor
__global__ void k_scan(int n) {
    __shared__ int sh[1024];
    __shared__ int carry;
    int t = threadIdx.x;
    if (t == 0) carry = 0;
    __syncthreads();
    for (int base = 0; base < n; base += 1024) {
        int i = base + t;
        int v = (i < n) ? g_degcnt[i] : 0;
        sh[t] = v;
        __syncthreads();
        for (int off = 1; off < 1024; off <<= 1) {
            int tv = (t >= off) ? sh[t - off] : 0;
            __syncthreads();
            sh[t] += tv;
            __syncthreads();
        }
        if (i < n) {
            int ex = carry + sh[t] - v;
            g_rowptr[i] = ex;
            g_cursor[i] = ex;
        }
        __syncthreads();
        if (t == 0) carry += sh[1023];
        __syncthreads();
    }
    if (t == 0) g_rowptr[n] = carry;
}

__global__ void k_fill(const int* __restrict__ dst, int E) {
    int e = blockIdx.x * blockDim.x + threadIdx.x;
    if (e >= E) return;
    int pos = atomicAdd(&g_cursor[dst[e]], 1);
    g_eord[pos] = e;
}

// ---------------- aggregation: one block per node, smem acc, no atomics -----
template <int CI, int WITH_S>
__global__ void k_agg(const float* __restrict__ X, const int* __restrict__ src, int ldacc) {
    extern __shared__ float acc[];      // KT*CI floats
    int n = blockIdx.x;
    int c = threadIdx.x;
    for (int i = c; i < KT * CI; i += CI) acc[i] = 0.f;
    int jb = g_rowptr[n], je = g_rowptr[n + 1];
    float invd = (je > jb) ? 1.f / (float)(je - jb) : 1.f;
    float ss = 0.f;
    for (int j = jb; j < je; j++) {
        int e = g_eord[j];
        float xv = X[(size_t)src[e] * CI + c];
        if (WITH_S) ss += xv;
#pragma unroll
        for (int m = 0; m < 8; m++) {
            int ki = g_idx8[e * 8 + m];
            float w = g_w8[e * 8 + m];
            acc[ki * CI + c] += w * xv;          // thread owns channel c: race-free
        }
    }
    size_t base = (size_t)n * ldacc;
    for (int i = c; i < KT * CI; i += CI) g_acc[base + i] = acc[i] * invd;
    g_acc[base + KT * CI + c] = X[(size_t)n * CI + c];   // root-weight rows (undivided)
    if (WITH_S) {
        g_sin[n * CC + c]       = ss * invd;             // mean aggregation for shortcut
        g_sin[n * CC + CI1 + c] = X[n * CI1 + c];        // root input
    }
}

__global__ void k_cat(float* __restrict__ d, const float* __restrict__ s1, int n1,
                      const float* __restrict__ s2, int n2) {
    int i = blockIdx.x * blockDim.x + threadIdx.x;
    if (i < n1) d[i] = s1[i];
    else if (i < n1 + n2) d[i] = s2[i - n1];
}

__global__ void k_initC(float* __restrict__ Cp, const float* __restrict__ bias, int n) {
    int i = blockIdx.x * blockDim.x + threadIdx.x;
    if (i < n) Cp[i] = bias[i & (CC - 1)];
}

// ---------------- fp32 SIMT GEMM: C += A[M,K] * B[K,128], split-K via atomics
__global__ __launch_bounds__(256, 2)
void k_gemm(const float* __restrict__ A, int lda, int M, int K,
            const float* __restrict__ B, float* __restrict__ Cp) {
    __shared__ float As[16][132];
    __shared__ float Bs[16][128];
    int tid = threadIdx.x;
    int m0 = blockIdx.x * 128;
    int itersTot = K / 16;
    int iters = itersTot / gridDim.y;
    int kbase = blockIdx.y * iters * 16;
    int ty = tid >> 4, tx = tid & 15;
    float accu[8][8];
#pragma unroll
    for (int i = 0; i < 8; i++)
#pragma unroll
        for (int j = 0; j < 8; j++) accu[i][j] = 0.f;
    int aRow = tid >> 2;           // 0..63 (and +64)
    int aK = (tid & 3) * 4;
    int bRow = tid >> 5;           // 0..7 (and +8)
    int bCol = (tid & 31) * 4;
    for (int it = 0; it < iters; it++) {
        int kb = kbase + it * 16;
        float4 a0 = make_float4(0.f, 0.f, 0.f, 0.f);
        float4 a1 = make_float4(0.f, 0.f, 0.f, 0.f);
        int r0 = m0 + aRow, r1 = m0 + aRow + 64;
        if (r0 < M) a0 = *(const float4*)&A[(size_t)r0 * lda + kb + aK];
        if (r1 < M) a1 = *(const float4*)&A[(size_t)r1 * lda + kb + aK];
        float4 b0 = *(const float4*)&B[(size_t)(kb + bRow) * CC + bCol];
        float4 b1 = *(const float4*)&B[(size_t)(kb + bRow + 8) * CC + bCol];
        __syncthreads();
        As[aK + 0][aRow] = a0.x; As[aK + 1][aRow] = a0.y;
        As[aK + 2][aRow] = a0.z; As[aK + 3][aRow] = a0.w;
        As[aK + 0][aRow + 64] = a1.x; As[aK + 1][aRow + 64] = a1.y;
        As[aK + 2][aRow + 64] = a1.z; As[aK + 3][aRow + 64] = a1.w;
        *(float4*)&Bs[bRow][bCol] = b0;
        *(float4*)&Bs[bRow + 8][bCol] = b1;
        __syncthreads();
#pragma unroll
        for (int kk = 0; kk < 16; kk++) {
            float av[8], bv[8];
            *(float4*)av       = *(float4*)&As[kk][ty * 8];
            *(float4*)(av + 4) = *(float4*)&As[kk][ty * 8 + 4];
            *(float4*)bv       = *(float4*)&Bs[kk][tx * 8];
            *(float4*)(bv + 4) = *(float4*)&Bs[kk][tx * 8 + 4];
#pragma unroll
            for (int i = 0; i < 8; i++)
#pragma unroll
                for (int j = 0; j < 8; j++) accu[i][j] += av[i] * bv[j];
        }
    }
#pragma unroll
    for (int i = 0; i < 8; i++) {
        int m = m0 + ty * 8 + i;
        if (m < M) {
#pragma unroll
            for (int j = 0; j < 8; j++)
                atomicAdd(&Cp[(size_t)m * CC + tx * 8 + j], accu[i][j]);
        }
    }
}

// ---------------- batch norm helpers ----------------------------------------
__global__ void k_colred(const float* __restrict__ X, int M, float* __restrict__ red) {
    int c = threadIdx.x;
    float s = 0.f, s2 = 0.f;
    for (int r = blockIdx.x; r < M; r += gridDim.x) {
        float v = X[(size_t)r * CC + c];
        s += v;
        s2 += v * v;
    }
    atomicAdd(&red[c], s);
    atomicAdd(&red[CC + c], s2);
}

__global__ void k_stats(const float* __restrict__ red, const float* __restrict__ g,
                        const float* __restrict__ be, float* __restrict__ sc,
                        float* __restrict__ sh, int M) {
    int c = threadIdx.x;
    float mu = red[c] / (float)M;
    float var = red[CC + c] / (float)M - mu * mu;
    float rs = rsqrtf(var + 1e-5f);
    float s = g[c] * rs;
    sc[c] = s;
    sh[c] = be[c] - mu * s;
}

__global__ void k_bnelu(const float* __restrict__ X, const float* __restrict__ sc,
                        const float* __restrict__ sh, float* __restrict__ Y, int n) {
    int i = blockIdx.x * blockDim.x + threadIdx.x;
    if (i >= n) return;
    int c = i & (CC - 1);
    float v = X[i] * sc[c] + sh[c];
    Y[i] = v > 0.f ? v : expm1f(v);
}

__global__ void k_final(const float* __restrict__ A, const float* __restrict__ B,
                        const float* __restrict__ sc2, const float* __restrict__ sh2,
                        const float* __restrict__ scS, const float* __restrict__ shS,
                        float* __restrict__ out, int n) {
    int i = blockIdx.x * blockDim.x + threadIdx.x;
    if (i >= n) return;
    int c = i & (CC - 1);
    float v = A[i] * sc2[c] + sh2[c] + B[i] * scS[c] + shS[c];
    out[i] = v > 0.f ? v : expm1f(v);
}

// ---------------- launch ----------------------------------------------------
extern "C" void kernel_launch(void* const* d_in, const int* in_sizes, int n_in,
                              void* d_out, int out_size) {
    const float* x    = (const float*)d_in[0];
    const int*   ei   = (const int*)d_in[1];
    const float* attr = (const float*)d_in[2];
    const float* W1   = (const float*)d_in[3];
    const float* Wr1  = (const float*)d_in[4];
    const float* b1   = (const float*)d_in[5];
    const float* g1   = (const float*)d_in[6];
    const float* be1  = (const float*)d_in[7];
    const float* W2   = (const float*)d_in[8];
    const float* Wr2  = (const float*)d_in[9];
    const float* b2   = (const float*)d_in[10];
    const float* g2   = (const float*)d_in[11];
    const float* be2  = (const float*)d_in[12];
    const float* Wsc  = (const float*)d_in[13];
    const float* Wrsc = (const float*)d_in[14];
    const float* bsc  = (const float*)d_in[15];
    const float* gsc  = (const float*)d_in[16];
    const float* besc = (const float*)d_in[17];

    int E = in_sizes[1] / 2;
    int M = in_sizes[0] / CI1;
    const int* src = ei;
    const int* dst = ei + E;

    float *acc, *wcat, *wcs, *out1, *h1e, *out2, *outs, *sinb, *red, *scale, *shift;
    cudaGetSymbolAddress((void**)&acc,   g_acc);
    cudaGetSymbolAddress((void**)&wcat,  g_wcat);
    cudaGetSymbolAddress((void**)&wcs,   g_wcs);
    cudaGetSymbolAddress((void**)&out1,  g_out1);
    cudaGetSymbolAddress((void**)&h1e,   g_h1e);
    cudaGetSymbolAddress((void**)&out2,  g_out2);
    cudaGetSymbolAddress((void**)&outs,  g_outs);
    cudaGetSymbolAddress((void**)&sinb,  g_sin);
    cudaGetSymbolAddress((void**)&red,   g_red);
    cudaGetSymbolAddress((void**)&scale, g_scale);
    cudaGetSymbolAddress((void**)&shift, g_shift);

    cudaFuncSetAttribute(k_agg<CC, 0>, cudaFuncAttributeMaxDynamicSharedMemorySize,
                         KT * CC * 4);

    int eb = (E + 255) / 256;

    // CSR build + per-edge spline basis
    k_zero<<<(M + 255) / 256, 256>>>(M);
    k_pre<<<eb, 256>>>(attr, dst, E);
    k_scan<<<1, 1024>>>(M);
    k_fill<<<eb, 256>>>(dst, E);

    // conv1 aggregation (+ fused shortcut mean aggregation)
    k_agg<CI1, 1><<<M, CI1, KT * CI1 * 4>>>(x, src, LD1);

    // conv1 GEMM
    k_cat<<<(LD1 * CC + 255) / 256, 256>>>(wcat, W1, KT * CI1 * CC, Wr1, CI1 * CC);
    k_initC<<<(M * CC + 255) / 256, 256>>>(out1, b1, M * CC);
    dim3 gg((M + 127) / 128, 4);
    k_gemm<<<gg, 256>>>(acc, LD1, M, LD1, wcat, out1);

    // bn1 + elu
    k_colred<<<256, CC>>>(out1, M, red);
    k_stats<<<1, CC>>>(red, g1, be1, scale, shift, M);
    k_bnelu<<<(M * CC + 255) / 256, 256>>>(out1, scale, shift, h1e, M * CC);

    // conv2 aggregation + GEMM
    k_agg<CC, 0><<<M, CC, KT * CC * 4>>>(h1e, src, LD2);
    k_cat<<<(LD2 * CC + 255) / 256, 256>>>(wcat, W2, KT * CC * CC, Wr2, CC * CC);
    k_initC<<<(M * CC + 255) / 256, 256>>>(out2, b2, M * CC);
    k_gemm<<<gg, 256>>>(acc, LD2, M, LD2, wcat, out2);

    // shortcut GEMM (K=1 splineconv == mean-agg @ Wsc + x @ Wrsc)
    k_cat<<<(CC * CC + 255) / 256, 256>>>(wcs, Wsc, CI1 * CC, Wrsc, CI1 * CC);
    k_initC<<<(M * CC + 255) / 256, 256>>>(outs, bsc, M * CC);
    dim3 gs((M + 127) / 128, 2);
    k_gemm<<<gs, 256>>>(sinb, CC, M, CC, wcs, outs);

    // bn2, bn_sc, final elu(h + s)
    k_colred<<<256, CC>>>(out2, M, red + 2 * CC);
    k_stats<<<1, CC>>>(red + 2 * CC, g2, be2, scale + CC, shift + CC, M);
    k_colred<<<256, CC>>>(outs, M, red + 4 * CC);
    k_stats<<<1, CC>>>(red + 4 * CC, gsc, besc, scale + 2 * CC, shift + 2 * CC, M);
    k_final<<<(M * CC + 255) / 256, 256>>>(out2, outs, scale + CC, shift + CC,
                                           scale + 2 * CC, shift + 2 * CC,
                                           (float*)d_out, M * CC);
}

// round 5
// speedup vs baseline: 1.9339x; 1.9339x over previous
#include <cuda_runtime.h>
#include <math.h>
#include <stdint.h>

#define NMAX 10000
#define EMAX 160000
#define KT   125
#define CI1  64
#define CC   128
#define LD1  (KT*CI1 + CI1)    // 8064
#define LD2  (KT*CC + CC)      // 16128

// ---------------- scratch (device globals: no allocations allowed) ----------
__device__ __align__(1024) float g_acc[(size_t)NMAX * LD2];   // 645MB
__device__ __align__(1024) float g_wt [CC * LD2];             // transposed weights [n][k]
__device__ __align__(1024) float g_out1[NMAX * CC];
__device__ __align__(1024) float g_h1e [NMAX * CC];
__device__ __align__(1024) float g_out2[NMAX * CC];
__device__ __align__(1024) float g_outs[NMAX * CC];
__device__ __align__(1024) float g_sin [NMAX * CC];           // [s_agg | x]
__device__ float g_w8  [EMAX * 8];
__device__ int   g_idx8[EMAX * 8];
__device__ int   g_eord[EMAX];
__device__ int   g_rowptr[NMAX + 1];
__device__ int   g_cursor[NMAX];
__device__ int   g_degcnt[NMAX];
__device__ float g_red  [6 * CC];
__device__ float g_scale[3 * CC];
__device__ float g_shift[3 * CC];

// ---------------- helpers ----------------------------------------------------
__device__ __forceinline__ uint32_t smem_u32(const void* p) {
    uint32_t a;
    asm("{ .reg .u64 t; cvta.to.shared.u64 t, %1; cvt.u32.u64 %0, t; }" : "=r"(a) : "l"(p));
    return a;
}
__device__ __forceinline__ float rtf32(float v) {
    uint32_t u; asm("cvt.rna.tf32.f32 %0, %1;" : "=r"(u) : "f"(v));
    return __uint_as_float(u);
}
__device__ __forceinline__ void cp_async16(uint32_t dst, const void* src, int vsize) {
    asm volatile("cp.async.cg.shared.global [%0], [%1], 16, %2;"
                 :: "r"(dst), "l"(src), "r"(vsize) : "memory");
}
#define CP_COMMIT() asm volatile("cp.async.commit_group;" ::: "memory")
#define CP_WAIT(n)  asm volatile("cp.async.wait_group %0;" :: "n"(n) : "memory")

__device__ __forceinline__ void mma_tf32(float* c, const uint32_t* a, uint32_t b0, uint32_t b1) {
    asm volatile("mma.sync.aligned.m16n8k8.row.col.f32.tf32.tf32.f32 "
                 "{%0,%1,%2,%3}, {%4,%5,%6,%7}, {%8,%9}, {%0,%1,%2,%3};"
                 : "+f"(c[0]), "+f"(c[1]), "+f"(c[2]), "+f"(c[3])
                 : "r"(a[0]), "r"(a[1]), "r"(a[2]), "r"(a[3]), "r"(b0), "r"(b1));
}

// ---------------- small kernels ---------------------------------------------
__global__ void k_zero(int n) {
    int i = blockIdx.x * blockDim.x + threadIdx.x;
    if (i < n) g_degcnt[i] = 0;
    if (i < 6 * CC) g_red[i] = 0.f;
}

__global__ void k_pre(const float* __restrict__ attr, const int* __restrict__ dst, int E) {
    int e = blockIdx.x * blockDim.x + threadIdx.x;
    if (e >= E) return;
    float v0 = attr[e * 3 + 0] * 4.f, v1 = attr[e * 3 + 1] * 4.f, v2 = attr[e * 3 + 2] * 4.f;
    float b0 = floorf(v0), b1 = floorf(v1), b2 = floorf(v2);
    float f0 = v0 - b0, f1 = v1 - b1, f2 = v2 - b2;
    int i0 = (int)b0, i1 = (int)b1, i2 = (int)b2;
#pragma unroll
    for (int m = 0; m < 8; m++) {
        int t0 = m & 1, t1 = (m >> 1) & 1, t2 = (m >> 2) & 1;
        float w = (t0 ? f0 : 1.f - f0) * (t1 ? f1 : 1.f - f1) * (t2 ? f2 : 1.f - f2);
        int c0 = min(max(i0 + t0, 0), 4);
        int c1 = min(max(i1 + t1, 0), 4);
        int c2 = min(max(i2 + t2, 0), 4);
        g_idx8[e * 8 + m] = (c0 * 5 + c1) * 5 + c2;
        g_w8[e * 8 + m] = w;
    }
    atomicAdd(&g_degcnt[dst[e]], 1);
}

__global__ void k_scan(int n) {
    __shared__ int sh[1024];
    __shared__ int carry;
    int t = threadIdx.x;
    if (t == 0) carry = 0;
    __syncthreads();
    for (int base = 0; base < n; base += 1024) {
        int i = base + t;
        int v = (i < n) ? g_degcnt[i] : 0;
        sh[t] = v;
        __syncthreads();
        for (int off = 1; off < 1024; off <<= 1) {
            int tv = (t >= off) ? sh[t - off] : 0;
            __syncthreads();
            sh[t] += tv;
            __syncthreads();
        }
        if (i < n) {
            int ex = carry + sh[t] - v;
            g_rowptr[i] = ex;
            g_cursor[i] = ex;
        }
        __syncthreads();
        if (t == 0) carry += sh[1023];
        __syncthreads();
    }
    if (t == 0) g_rowptr[n] = carry;
}

__global__ void k_fill(const int* __restrict__ dst, int E) {
    int e = blockIdx.x * blockDim.x + threadIdx.x;
    if (e >= E) return;
    int pos = atomicAdd(&g_cursor[dst[e]], 1);
    g_eord[pos] = e;
}

// ---------------- aggregation -----------------------------------------------
template <int CI, int WITH_S>
__global__ void k_agg(const float* __restrict__ X, const int* __restrict__ src, int ldacc) {
    extern __shared__ float acc[];
    int n = blockIdx.x;
    int c = threadIdx.x;
    for (int i = c; i < KT * CI; i += CI) acc[i] = 0.f;
    int jb = g_rowptr[n], je = g_rowptr[n + 1];
    float invd = (je > jb) ? 1.f / (float)(je - jb) : 1.f;
    float ss = 0.f;
    for (int j = jb; j < je; j++) {
        int e = g_eord[j];
        float xv = X[(size_t)src[e] * CI + c];
        if (WITH_S) ss += xv;
#pragma unroll
        for (int m = 0; m < 8; m++) {
            int ki = g_idx8[e * 8 + m];
            float w = g_w8[e * 8 + m];
            acc[ki * CI + c] += w * xv;
        }
    }
    size_t base = (size_t)n * ldacc;
    for (int i = c; i < KT * CI; i += CI) g_acc[base + i] = rtf32(acc[i] * invd);
    g_acc[base + KT * CI + c] = rtf32(X[(size_t)n * CI + c]);
    if (WITH_S) {
        g_sin[n * CC + c]       = rtf32(ss * invd);
        g_sin[n * CC + CI1 + c] = rtf32(X[n * CI1 + c]);
    }
}

// transpose weights into wt[n][k] (tf32-rounded)
__global__ void k_transp(const float* __restrict__ W, const float* __restrict__ Wr,
                         int Kmain, int Ktot, float* __restrict__ wt) {
    int k = blockIdx.x * blockDim.x + threadIdx.x;
    int n = blockIdx.y;
    if (k >= Ktot) return;
    float v = (k < Kmain) ? W[(size_t)k * CC + n] : Wr[(size_t)(k - Kmain) * CC + n];
    wt[(size_t)n * Ktot + k] = rtf32(v);
}

__global__ void k_initC(float* __restrict__ Cp, const float* __restrict__ bias, int n) {
    int i = blockIdx.x * blockDim.x + threadIdx.x;
    if (i < n) Cp[i] = bias[i & (CC - 1)];
}

// ---------------- tf32 mma.sync GEMM: C += A[M,K] * wt[128,K]^T ---------------
// CTA: 128(M) x 128(N), K-chunk 32, 8 warps (warp tile 32x64), 4-stage cp.async.
// SMEM tiles XOR-swizzled:  offset(m,k) = m*32 + (k ^ ((m&7)<<2))  (floats).
#define BK 32
#define NSTAGE 4
#define STGF 4096   // floats per A (or B) tile: 128*32

__global__ __launch_bounds__(256, 1)
void k_mgemm(const float* __restrict__ A, const float* __restrict__ B, int ld,
             int M, float* __restrict__ Cp, int chunks) {
    extern __shared__ float sm[];   // [NSTAGE][A(4096) | B(4096)]
    int tid = threadIdx.x, lane = tid & 31, wid = tid >> 5;
    int m0 = blockIdx.x * 128;
    int kb0 = blockIdx.y * chunks * BK;

    // producer mapping: thread -> (row = tid>>1, k-half = (tid&1)*16), 4 float4 each
    int pr_m = tid >> 1;
    int pr_kh = (tid & 1) * 16;
    int pr_sw = (pr_m & 7) << 2;
    int grow = m0 + pr_m;
    int vA = (grow < M) ? 16 : 0;

    const int warp_m0 = (wid & 3) * 32;
    const int warp_n0 = (wid >> 2) * 64;
    int qr = lane >> 2, qc = lane & 3;
    int swz = lane & 28;                 // (lane>>2)<<2

    float c[2][8][4];
#pragma unroll
    for (int i = 0; i < 2; i++)
#pragma unroll
        for (int j = 0; j < 8; j++)
#pragma unroll
            for (int t = 0; t < 4; t++) c[i][j][t] = 0.f;

    uint32_t smb = smem_u32(sm);

#define ISSUE(IT) do { \
    int _it = (IT); \
    if (_it < chunks) { \
        int _s = _it & (NSTAGE - 1); \
        uint32_t _dA = smb + _s * (2 * STGF) * 4; \
        uint32_t _dB = _dA + STGF * 4; \
        int _kb = kb0 + _it * BK; \
        const float* _sa = A + (size_t)grow * ld + _kb + pr_kh; \
        const float* _sb = B + (size_t)pr_m * ld + _kb + pr_kh; \
        _Pragma("unroll") \
        for (int _j = 0; _j < 4; _j++) { \
            int _ko = pr_kh + _j * 4; \
            int _so = (pr_m * 32 + (_ko ^ pr_sw)) * 4; \
            cp_async16(_dA + _so, _sa + _j * 4, vA); \
            cp_async16(_dB + _so, _sb + _j * 4, 16); \
        } \
    } \
    CP_COMMIT(); \
} while (0)

    ISSUE(0); ISSUE(1); ISSUE(2);

    for (int it = 0; it < chunks; it++) {
        CP_WAIT(2);
        __syncthreads();
        ISSUE(it + 3);
        int s = it & (NSTAGE - 1);
        const float* sA = sm + s * (2 * STGF);
        const float* sB = sA + STGF;
#pragma unroll
        for (int ks = 0; ks < 4; ks++) {
            int k8 = ks * 8;
            int kA = (k8 + qc) ^ swz;
            int kB = (k8 + qc + 4) ^ swz;
            uint32_t a[2][4];
#pragma unroll
            for (int mf = 0; mf < 2; mf++) {
                int ro = (warp_m0 + mf * 16 + qr) * 32;
                a[mf][0] = __float_as_uint(sA[ro + kA]);
                a[mf][1] = __float_as_uint(sA[ro + 256 + kA]);   // row+8
                a[mf][2] = __float_as_uint(sA[ro + kB]);
                a[mf][3] = __float_as_uint(sA[ro + 256 + kB]);
            }
#pragma unroll
            for (int nf = 0; nf < 8; nf++) {
                int no = (warp_n0 + nf * 8 + qr) * 32;
                uint32_t b0 = __float_as_uint(sB[no + kA]);
                uint32_t b1 = __float_as_uint(sB[no + kB]);
                mma_tf32(c[0][nf], a[0], b0, b1);
                mma_tf32(c[1][nf], a[1], b0, b1);
            }
        }
        __syncthreads();
    }
    CP_WAIT(0);

#pragma unroll
    for (int mf = 0; mf < 2; mf++) {
        int r0 = m0 + warp_m0 + mf * 16 + qr;
#pragma unroll
        for (int nf = 0; nf < 8; nf++) {
            int col = warp_n0 + nf * 8 + qc * 2;
            if (r0 < M) {
                atomicAdd(&Cp[(size_t)r0 * CC + col],     c[mf][nf][0]);
                atomicAdd(&Cp[(size_t)r0 * CC + col + 1], c[mf][nf][1]);
            }
            if (r0 + 8 < M) {
                atomicAdd(&Cp[(size_t)(r0 + 8) * CC + col],     c[mf][nf][2]);
                atomicAdd(&Cp[(size_t)(r0 + 8) * CC + col + 1], c[mf][nf][3]);
            }
        }
    }
#undef ISSUE
}

// ---------------- batch norm ------------------------------------------------
__global__ void k_colred(const float* __restrict__ X, int M, float* __restrict__ red) {
    int c = threadIdx.x;
    float s = 0.f, s2 = 0.f;
    for (int r = blockIdx.x; r < M; r += gridDim.x) {
        float v = X[(size_t)r * CC + c];
        s += v; s2 += v * v;
    }
    atomicAdd(&red[c], s);
    atomicAdd(&red[CC + c], s2);
}

__global__ void k_stats(const float* __restrict__ red, const float* __restrict__ g,
                        const float* __restrict__ be, float* __restrict__ sc,
                        float* __restrict__ sh, int M) {
    int c = threadIdx.x;
    float mu = red[c] / (float)M;
    float var = red[CC + c] / (float)M - mu * mu;
    float s = g[c] * rsqrtf(var + 1e-5f);
    sc[c] = s;
    sh[c] = be[c] - mu * s;
}

__global__ void k_bnelu(const float* __restrict__ X, const float* __restrict__ sc,
                        const float* __restrict__ sh, float* __restrict__ Y, int n) {
    int i = blockIdx.x * blockDim.x + threadIdx.x;
    if (i >= n) return;
    int c = i & (CC - 1);
    float v = X[i] * sc[c] + sh[c];
    Y[i] = v > 0.f ? v : expm1f(v);
}

__global__ void k_final(const float* __restrict__ A, const float* __restrict__ B,
                        const float* __restrict__ sc2, const float* __restrict__ sh2,
                        const float* __restrict__ scS, const float* __restrict__ shS,
                        float* __restrict__ out, int n) {
    int i = blockIdx.x * blockDim.x + threadIdx.x;
    if (i >= n) return;
    int c = i & (CC - 1);
    float v = A[i] * sc2[c] + sh2[c] + B[i] * scS[c] + shS[c];
    out[i] = v > 0.f ? v : expm1f(v);
}

// ---------------- launch ----------------------------------------------------
extern "C" void kernel_launch(void* const* d_in, const int* in_sizes, int n_in,
                              void* d_out, int out_size) {
    const float* x    = (const float*)d_in[0];
    const int*   ei   = (const int*)d_in[1];
    const float* attr = (const float*)d_in[2];
    const float* W1   = (const float*)d_in[3];
    const float* Wr1  = (const float*)d_in[4];
    const float* b1   = (const float*)d_in[5];
    const float* g1   = (const float*)d_in[6];
    const float* be1  = (const float*)d_in[7];
    const float* W2   = (const float*)d_in[8];
    const float* Wr2  = (const float*)d_in[9];
    const float* b2   = (const float*)d_in[10];
    const float* g2   = (const float*)d_in[11];
    const float* be2  = (const float*)d_in[12];
    const float* Wsc  = (const float*)d_in[13];
    const float* Wrsc = (const float*)d_in[14];
    const float* bsc  = (const float*)d_in[15];
    const float* gsc  = (const float*)d_in[16];
    const float* besc = (const float*)d_in[17];

    int E = in_sizes[1] / 2;
    int M = in_sizes[0] / CI1;
    const int* src = ei;
    const int* dst = ei + E;

    float *acc, *wt, *out1, *h1e, *out2, *outs, *sinb, *red, *scale, *shift;
    cudaGetSymbolAddress((void**)&acc,   g_acc);
    cudaGetSymbolAddress((void**)&wt,    g_wt);
    cudaGetSymbolAddress((void**)&out1,  g_out1);
    cudaGetSymbolAddress((void**)&h1e,   g_h1e);
    cudaGetSymbolAddress((void**)&out2,  g_out2);
    cudaGetSymbolAddress((void**)&outs,  g_outs);
    cudaGetSymbolAddress((void**)&sinb,  g_sin);
    cudaGetSymbolAddress((void**)&red,   g_red);
    cudaGetSymbolAddress((void**)&scale, g_scale);
    cudaGetSymbolAddress((void**)&shift, g_shift);

    cudaFuncSetAttribute(k_agg<CC, 0>, cudaFuncAttributeMaxDynamicSharedMemorySize, KT * CC * 4);
    int dsm = NSTAGE * 2 * STGF * 4;   // 128KB
    cudaFuncSetAttribute(k_mgemm, cudaFuncAttributeMaxDynamicSharedMemorySize, dsm);

    int eb = (E + 255) / 256;
    int mtiles = (M + 127) / 128;

    // CSR build + spline basis
    k_zero<<<(M + 255) / 256, 256>>>(M);
    k_pre<<<eb, 256>>>(attr, dst, E);
    k_scan<<<1, 1024>>>(M);
    k_fill<<<eb, 256>>>(dst, E);

    // conv1: aggregate (+fused shortcut agg), transpose weights, GEMM
    k_agg<CI1, 1><<<M, CI1, KT * CI1 * 4>>>(x, src, LD1);
    k_transp<<<dim3((LD1 + 255) / 256, CC), 256>>>(W1, Wr1, KT * CI1, LD1, wt);
    k_initC<<<(M * CC + 255) / 256, 256>>>(out1, b1, M * CC);
    k_mgemm<<<dim3(mtiles, 2), 256, dsm>>>(acc, wt, LD1, M, out1, (LD1 / BK) / 2);

    // bn1 + elu
    k_colred<<<256, CC>>>(out1, M, red);
    k_stats<<<1, CC>>>(red, g1, be1, scale, shift, M);
    k_bnelu<<<(M * CC + 255) / 256, 256>>>(out1, scale, shift, h1e, M * CC);

    // conv2
    k_agg<CC, 0><<<M, CC, KT * CC * 4>>>(h1e, src, LD2);
    k_transp<<<dim3((LD2 + 255) / 256, CC), 256>>>(W2, Wr2, KT * CC, LD2, wt);
    k_initC<<<(M * CC + 255) / 256, 256>>>(out2, b2, M * CC);
    k_mgemm<<<dim3(mtiles, 2), 256, dsm>>>(acc, wt, LD2, M, out2, (LD2 / BK) / 2);

    // shortcut: [mean_agg | x] @ [Wsc ; Wrsc]
    k_transp<<<dim3((CC + 255) / 256, CC), 256>>>(Wsc, Wrsc, CI1, CC, wt);
    k_initC<<<(M * CC + 255) / 256, 256>>>(outs, bsc, M * CC);
    k_mgemm<<<dim3(mtiles, 1), 256, dsm>>>(sinb, wt, CC, M, outs, CC / BK);

    // bn2, bn_sc, final elu(h + s)
    k_colred<<<256, CC>>>(out2, M, red + 2 * CC);
    k_stats<<<1, CC>>>(red + 2 * CC, g2, be2, scale + CC, shift + CC, M);
    k_colred<<<256, CC>>>(outs, M, red + 4 * CC);
    k_stats<<<1, CC>>>(red + 4 * CC, gsc, besc, scale + 2 * CC, shift + 2 * CC, M);
    k_final<<<(M * CC + 255) / 256, 256>>>(out2, outs, scale + CC, shift + CC,
                                           scale + 2 * CC, shift + 2 * CC,
                                           (float*)d_out, M * CC);
}

// round 6
// speedup vs baseline: 3.3831x; 1.7494x over previous
#include <cuda_runtime.h>
#include <cuda_fp16.h>
#include <math.h>
#include <stdint.h>

#define NMAX 10000
#define EMAX 160000
#define KT   125
#define CI1  64
#define CC   128
#define LD1  (KT*CI1 + CI1)    // 8064
#define LD2  (KT*CC + CC)      // 16128

// ---------------- scratch (device globals: no allocations allowed) ----------
__device__ __align__(1024) __half g_acc[(size_t)NMAX * LD2];  // 322MB
__device__ __align__(1024) __half g_wt [CC * LD2];            // transposed weights [n][k]
__device__ __align__(1024) __half g_sin[NMAX * CC];           // [s_agg | x] shortcut A
__device__ __align__(1024) float g_out1[NMAX * CC];
__device__ __align__(1024) float g_h1e [NMAX * CC];
__device__ __align__(1024) float g_out2[NMAX * CC];
__device__ __align__(1024) float g_outs[NMAX * CC];
__device__ float g_w8  [EMAX * 8];
__device__ int   g_idx8[EMAX * 8];
__device__ int   g_eord[EMAX];
__device__ int   g_rowptr[NMAX + 1];
__device__ int   g_cursor[NMAX];
__device__ int   g_degcnt[NMAX];
__device__ float g_red  [6 * CC];
__device__ float g_scale[3 * CC];
__device__ float g_shift[3 * CC];

// ---------------- helpers ----------------------------------------------------
__device__ __forceinline__ uint32_t smem_u32(const void* p) {
    uint32_t a;
    asm("{ .reg .u64 t; cvta.to.shared.u64 t, %1; cvt.u32.u64 %0, t; }" : "=r"(a) : "l"(p));
    return a;
}
__device__ __forceinline__ void cp_async16(uint32_t dst, const void* src, int vsize) {
    asm volatile("cp.async.cg.shared.global [%0], [%1], 16, %2;"
                 :: "r"(dst), "l"(src), "r"(vsize) : "memory");
}
#define CP_COMMIT() asm volatile("cp.async.commit_group;" ::: "memory")
#define CP_WAIT(n)  asm volatile("cp.async.wait_group %0;" :: "n"(n) : "memory")

// fp16 MMA, fp32 accumulate
__device__ __forceinline__ void mma_f16(float* c, const uint32_t* a, uint32_t b0, uint32_t b1) {
    asm volatile("mma.sync.aligned.m16n8k16.row.col.f32.f16.f16.f32 "
                 "{%0,%1,%2,%3}, {%4,%5,%6,%7}, {%8,%9}, {%0,%1,%2,%3};"
                 : "+f"(c[0]), "+f"(c[1]), "+f"(c[2]), "+f"(c[3])
                 : "r"(a[0]), "r"(a[1]), "r"(a[2]), "r"(a[3]), "r"(b0), "r"(b1));
}

// ---------------- small kernels ---------------------------------------------
__global__ void k_zero(int n) {
    int i = blockIdx.x * blockDim.x + threadIdx.x;
    if (i < n) g_degcnt[i] = 0;
    if (i < 6 * CC) g_red[i] = 0.f;
}

__global__ void k_pre(const float* __restrict__ attr, const int* __restrict__ dst, int E) {
    int e = blockIdx.x * blockDim.x + threadIdx.x;
    if (e >= E) return;
    float v0 = attr[e * 3 + 0] * 4.f, v1 = attr[e * 3 + 1] * 4.f, v2 = attr[e * 3 + 2] * 4.f;
    float b0 = floorf(v0), b1 = floorf(v1), b2 = floorf(v2);
    float f0 = v0 - b0, f1 = v1 - b1, f2 = v2 - b2;
    int i0 = (int)b0, i1 = (int)b1, i2 = (int)b2;
#pragma unroll
    for (int m = 0; m < 8; m++) {
        int t0 = m & 1, t1 = (m >> 1) & 1, t2 = (m >> 2) & 1;
        float w = (t0 ? f0 : 1.f - f0) * (t1 ? f1 : 1.f - f1) * (t2 ? f2 : 1.f - f2);
        int c0 = min(max(i0 + t0, 0), 4);
        int c1 = min(max(i1 + t1, 0), 4);
        int c2 = min(max(i2 + t2, 0), 4);
        g_idx8[e * 8 + m] = (c0 * 5 + c1) * 5 + c2;
        g_w8[e * 8 + m] = w;
    }
    atomicAdd(&g_degcnt[dst[e]], 1);
}

__global__ void k_scan(int n) {
    __shared__ int sh[1024];
    __shared__ int carry;
    int t = threadIdx.x;
    if (t == 0) carry = 0;
    __syncthreads();
    for (int base = 0; base < n; base += 1024) {
        int i = base + t;
        int v = (i < n) ? g_degcnt[i] : 0;
        sh[t] = v;
        __syncthreads();
        for (int off = 1; off < 1024; off <<= 1) {
            int tv = (t >= off) ? sh[t - off] : 0;
            __syncthreads();
            sh[t] += tv;
            __syncthreads();
        }
        if (i < n) {
            int ex = carry + sh[t] - v;
            g_rowptr[i] = ex;
            g_cursor[i] = ex;
        }
        __syncthreads();
        if (t == 0) carry += sh[1023];
        __syncthreads();
    }
    if (t == 0) g_rowptr[n] = carry;
}

__global__ void k_fill(const int* __restrict__ dst, int E) {
    int e = blockIdx.x * blockDim.x + threadIdx.x;
    if (e >= E) return;
    int pos = atomicAdd(&g_cursor[dst[e]], 1);
    g_eord[pos] = e;
}

// ---------------- aggregation -----------------------------------------------
template <int CI, int WITH_S>
__global__ void k_agg(const float* __restrict__ X, const int* __restrict__ src, int ldacc) {
    extern __shared__ float acc[];
    int n = blockIdx.x;
    int c = threadIdx.x;
    for (int i = c; i < KT * CI; i += CI) acc[i] = 0.f;
    int jb = g_rowptr[n], je = g_rowptr[n + 1];
    float invd = (je > jb) ? 1.f / (float)(je - jb) : 1.f;
    float ss = 0.f;
    for (int j = jb; j < je; j++) {
        int e = g_eord[j];
        float xv = X[(size_t)src[e] * CI + c];
        if (WITH_S) ss += xv;
#pragma unroll
        for (int m = 0; m < 8; m++) {
            int ki = g_idx8[e * 8 + m];
            float w = g_w8[e * 8 + m];
            acc[ki * CI + c] += w * xv;
        }
    }
    size_t base = (size_t)n * ldacc;
    for (int i = c; i < KT * CI; i += CI) g_acc[base + i] = __float2half(acc[i] * invd);
    g_acc[base + KT * CI + c] = __float2half(X[(size_t)n * CI + c]);
    if (WITH_S) {
        g_sin[n * CC + c]       = __float2half(ss * invd);
        g_sin[n * CC + CI1 + c] = __float2half(X[n * CI1 + c]);
    }
}

// transpose weights into wt[n][k] (fp16)
__global__ void k_transp(const float* __restrict__ W, const float* __restrict__ Wr,
                         int Kmain, int Ktot, __half* __restrict__ wt) {
    int k = blockIdx.x * blockDim.x + threadIdx.x;
    int n = blockIdx.y;
    if (k >= Ktot) return;
    float v = (k < Kmain) ? W[(size_t)k * CC + n] : Wr[(size_t)(k - Kmain) * CC + n];
    wt[(size_t)n * Ktot + k] = __float2half(v);
}

__global__ void k_initC(float* __restrict__ Cp, const float* __restrict__ bias, int n) {
    int i = blockIdx.x * blockDim.x + threadIdx.x;
    if (i < n) Cp[i] = bias[i & (CC - 1)];
}

// ---------------- fp16 mma.sync GEMM: C += A[M,K] * wt[128,K]^T ---------------
// CTA 128(M)x128(N), K-chunk 64 halves, 8 warps (warp tile 32x64), 3-stage cp.async.
// SMEM: per stage A(16KB)+B(16KB); rows of 128B (8 chunks of 16B), chunk XOR (row&7).
#define BK 64
#define NSTAGE 3
#define STG_BYTES 32768
#define TILE_BYTES 16384

__global__ __launch_bounds__(256, 2)
void k_mgemm(const __half* __restrict__ A, const __half* __restrict__ B, int ld,
             int M, float* __restrict__ Cp, int chunks) {
    extern __shared__ char sm[];
    int tid = threadIdx.x, lane = tid & 31, wid = tid >> 5;
    int m0 = blockIdx.x * 128;
    int kb0 = blockIdx.y * chunks * BK;

    // producer: thread -> row = tid>>1 (0..127), chunk set = (tid&1)*4 + j
    int pr_r = tid >> 1;
    int pr_h = (tid & 1) * 4;
    int grow = m0 + pr_r;
    int vA = (grow < M) ? 16 : 0;
    const __half* Abase = A + (size_t)grow * ld + kb0;
    const __half* Bbase = B + (size_t)pr_r * ld + kb0;

    const int warp_m0 = (wid & 3) * 32;
    const int warp_n0 = (wid >> 2) * 64;
    int g = lane >> 2, t = lane & 3;

    float c[2][8][4];
#pragma unroll
    for (int i = 0; i < 2; i++)
#pragma unroll
        for (int j = 0; j < 8; j++)
#pragma unroll
            for (int q = 0; q < 4; q++) c[i][j][q] = 0.f;

    uint32_t smb = smem_u32(sm);

#define ISSUE(IT) do { \
    int _it = (IT); \
    if (_it < chunks) { \
        int _s = _it % NSTAGE; \
        uint32_t _dA = smb + _s * STG_BYTES + pr_r * 128; \
        uint32_t _dB = _dA + TILE_BYTES; \
        const __half* _sa = Abase + _it * BK; \
        const __half* _sb = Bbase + _it * BK; \
        _Pragma("unroll") \
        for (int _j = 0; _j < 4; _j++) { \
            int _c = pr_h + _j; \
            int _sc = _c ^ (pr_r & 7); \
            cp_async16(_dA + _sc * 16, _sa + _c * 8, vA); \
            cp_async16(_dB + _sc * 16, _sb + _c * 8, 16); \
        } \
    } \
    CP_COMMIT(); \
} while (0)

    ISSUE(0); ISSUE(1);

    for (int it = 0; it < chunks; it++) {
        CP_WAIT(1);
        __syncthreads();
        ISSUE(it + 2);
        const char* sA = sm + (it % NSTAGE) * STG_BYTES;
        const char* sB = sA + TILE_BYTES;
        // pair index p (0..31): addr = row*128 + ((p>>2 ^ (row&7))*4 + (p&3))*4
#define LDP(base, row, p) (*(const uint32_t*)((base) + (row) * 128 + ((((p) >> 2) ^ ((row) & 7)) * 16) + ((p) & 3) * 4))
#pragma unroll
        for (int ks = 0; ks < 4; ks++) {
            int p0 = ks * 8 + t;
            uint32_t a[2][4];
#pragma unroll
            for (int mf = 0; mf < 2; mf++) {
                int r = warp_m0 + mf * 16 + g;
                a[mf][0] = LDP(sA, r,     p0);
                a[mf][1] = LDP(sA, r + 8, p0);
                a[mf][2] = LDP(sA, r,     p0 + 4);
                a[mf][3] = LDP(sA, r + 8, p0 + 4);
            }
#pragma unroll
            for (int nf = 0; nf < 8; nf++) {
                int nr = warp_n0 + nf * 8 + g;
                uint32_t b0 = LDP(sB, nr, p0);
                uint32_t b1 = LDP(sB, nr, p0 + 4);
                mma_f16(c[0][nf], a[0], b0, b1);
                mma_f16(c[1][nf], a[1], b0, b1);
            }
        }
#undef LDP
        __syncthreads();
    }
    CP_WAIT(0);

#pragma unroll
    for (int mf = 0; mf < 2; mf++) {
        int r0 = m0 + warp_m0 + mf * 16 + g;
#pragma unroll
        for (int nf = 0; nf < 8; nf++) {
            int col = warp_n0 + nf * 8 + t * 2;
            if (r0 < M) {
                atomicAdd(&Cp[(size_t)r0 * CC + col],     c[mf][nf][0]);
                atomicAdd(&Cp[(size_t)r0 * CC + col + 1], c[mf][nf][1]);
            }
            if (r0 + 8 < M) {
                atomicAdd(&Cp[(size_t)(r0 + 8) * CC + col],     c[mf][nf][2]);
                atomicAdd(&Cp[(size_t)(r0 + 8) * CC + col + 1], c[mf][nf][3]);
            }
        }
    }
#undef ISSUE
}

// ---------------- batch norm ------------------------------------------------
__global__ void k_colred(const float* __restrict__ X, int M, float* __restrict__ red) {
    int c = threadIdx.x;
    float s = 0.f, s2 = 0.f;
    for (int r = blockIdx.x; r < M; r += gridDim.x) {
        float v = X[(size_t)r * CC + c];
        s += v; s2 += v * v;
    }
    atomicAdd(&red[c], s);
    atomicAdd(&red[CC + c], s2);
}

__global__ void k_stats(const float* __restrict__ red, const float* __restrict__ g,
                        const float* __restrict__ be, float* __restrict__ sc,
                        float* __restrict__ sh, int M) {
    int c = threadIdx.x;
    float mu = red[c] / (float)M;
    float var = red[CC + c] / (float)M - mu * mu;
    float s = g[c] * rsqrtf(var + 1e-5f);
    sc[c] = s;
    sh[c] = be[c] - mu * s;
}

__global__ void k_bnelu(const float* __restrict__ X, const float* __restrict__ sc,
                        const float* __restrict__ sh, float* __restrict__ Y, int n) {
    int i = blockIdx.x * blockDim.x + threadIdx.x;
    if (i >= n) return;
    int c = i & (CC - 1);
    float v = X[i] * sc[c] + sh[c];
    Y[i] = v > 0.f ? v : expm1f(v);
}

__global__ void k_final(const float* __restrict__ A, const float* __restrict__ B,
                        const float* __restrict__ sc2, const float* __restrict__ sh2,
                        const float* __restrict__ scS, const float* __restrict__ shS,
                        float* __restrict__ out, int n) {
    int i = blockIdx.x * blockDim.x + threadIdx.x;
    if (i >= n) return;
    int c = i & (CC - 1);
    float v = A[i] * sc2[c] + sh2[c] + B[i] * scS[c] + shS[c];
    out[i] = v > 0.f ? v : expm1f(v);
}

// ---------------- launch ----------------------------------------------------
extern "C" void kernel_launch(void* const* d_in, const int* in_sizes, int n_in,
                              void* d_out, int out_size) {
    const float* x    = (const float*)d_in[0];
    const int*   ei   = (const int*)d_in[1];
    const float* attr = (const float*)d_in[2];
    const float* W1   = (const float*)d_in[3];
    const float* Wr1  = (const float*)d_in[4];
    const float* b1   = (const float*)d_in[5];
    const float* g1   = (const float*)d_in[6];
    const float* be1  = (const float*)d_in[7];
    const float* W2   = (const float*)d_in[8];
    const float* Wr2  = (const float*)d_in[9];
    const float* b2   = (const float*)d_in[10];
    const float* g2   = (const float*)d_in[11];
    const float* be2  = (const float*)d_in[12];
    const float* Wsc  = (const float*)d_in[13];
    const float* Wrsc = (const float*)d_in[14];
    const float* bsc  = (const float*)d_in[15];
    const float* gsc  = (const float*)d_in[16];
    const float* besc = (const float*)d_in[17];

    int E = in_sizes[1] / 2;
    int M = in_sizes[0] / CI1;
    const int* src = ei;
    const int* dst = ei + E;

    __half *acc, *wt, *sinb;
    float *out1, *h1e, *out2, *outs, *red, *scale, *shift;
    cudaGetSymbolAddress((void**)&acc,   g_acc);
    cudaGetSymbolAddress((void**)&wt,    g_wt);
    cudaGetSymbolAddress((void**)&sinb,  g_sin);
    cudaGetSymbolAddress((void**)&out1,  g_out1);
    cudaGetSymbolAddress((void**)&h1e,   g_h1e);
    cudaGetSymbolAddress((void**)&out2,  g_out2);
    cudaGetSymbolAddress((void**)&outs,  g_outs);
    cudaGetSymbolAddress((void**)&red,   g_red);
    cudaGetSymbolAddress((void**)&scale, g_scale);
    cudaGetSymbolAddress((void**)&shift, g_shift);

    cudaFuncSetAttribute(k_agg<CC, 0>, cudaFuncAttributeMaxDynamicSharedMemorySize, KT * CC * 4);
    int dsm = NSTAGE * STG_BYTES;   // 96KB
    cudaFuncSetAttribute(k_mgemm, cudaFuncAttributeMaxDynamicSharedMemorySize, dsm);

    int eb = (E + 255) / 256;
    int mtiles = (M + 127) / 128;

    // CSR build + spline basis
    k_zero<<<(M + 255) / 256, 256>>>(M);
    k_pre<<<eb, 256>>>(attr, dst, E);
    k_scan<<<1, 1024>>>(M);
    k_fill<<<eb, 256>>>(dst, E);

    // conv1: aggregate (+fused shortcut agg), transpose weights, GEMM (splitK=3)
    k_agg<CI1, 1><<<M, CI1, KT * CI1 * 4>>>(x, src, LD1);
    k_transp<<<dim3((LD1 + 255) / 256, CC), 256>>>(W1, Wr1, KT * CI1, LD1, wt);
    k_initC<<<(M * CC + 255) / 256, 256>>>(out1, b1, M * CC);
    k_mgemm<<<dim3(mtiles, 3), 256, dsm>>>(acc, wt, LD1, M, out1, (LD1 / BK) / 3);

    // bn1 + elu
    k_colred<<<256, CC>>>(out1, M, red);
    k_stats<<<1, CC>>>(red, g1, be1, scale, shift, M);
    k_bnelu<<<(M * CC + 255) / 256, 256>>>(out1, scale, shift, h1e, M * CC);

    // conv2 (splitK=4)
    k_agg<CC, 0><<<M, CC, KT * CC * 4>>>(h1e, src, LD2);
    k_transp<<<dim3((LD2 + 255) / 256, CC), 256>>>(W2, Wr2, KT * CC, LD2, wt);
    k_initC<<<(M * CC + 255) / 256, 256>>>(out2, b2, M * CC);
    k_mgemm<<<dim3(mtiles, 4), 256, dsm>>>(acc, wt, LD2, M, out2, (LD2 / BK) / 4);

    // shortcut: [mean_agg | x] @ [Wsc ; Wrsc]
    k_transp<<<dim3((CC + 255) / 256, CC), 256>>>(Wsc, Wrsc, CI1, CC, wt);
    k_initC<<<(M * CC + 255) / 256, 256>>>(outs, bsc, M * CC);
    k_mgemm<<<dim3(mtiles, 1), 256, dsm>>>(sinb, wt, CC, M, outs, CC / BK);

    // bn2, bn_sc, final elu(h + s)
    k_colred<<<256, CC>>>(out2, M, red + 2 * CC);
    k_stats<<<1, CC>>>(red + 2 * CC, g2, be2, scale + CC, shift + CC, M);
    k_colred<<<256, CC>>>(outs, M, red + 4 * CC);
    k_stats<<<1, CC>>>(red + 4 * CC, gsc, besc, scale + 2 * CC, shift + 2 * CC, M);
    k_final<<<(M * CC + 255) / 256, 256>>>(out2, outs, scale + CC, shift + CC,
                                           scale + 2 * CC, shift + 2 * CC,
                                           (float*)d_out, M * CC);
}

// round 8
// speedup vs baseline: 3.7003x; 1.0937x over previous
#include <cuda_runtime.h>
#include <cuda_fp16.h>
#include <math.h>
#include <stdint.h>

#define NMAX 10000
#define EMAX 160000
#define KT   125
#define CI1  64
#define CC   128
#define LD1  (KT*CI1 + CI1)    // 8064
#define LD2  (KT*CC + CC)      // 16128

// ---------------- scratch (device globals: no allocations allowed) ----------
__device__ __align__(1024) __half g_acc[(size_t)NMAX * LD2];  // 322MB
__device__ __align__(1024) __half g_wt [CC * LD2];            // transposed weights [n][k]
__device__ __align__(1024) __half g_sin[NMAX * CC];           // [s_agg | x] shortcut A
__device__ __align__(1024) float g_part[3 * (size_t)NMAX * CC]; // split-K partials
__device__ __align__(1024) float g_out1[NMAX * CC];
__device__ __align__(1024) float g_h1e [NMAX * CC];
__device__ __align__(1024) float g_out2[NMAX * CC];
__device__ __align__(1024) float g_outs[NMAX * CC];
__device__ float g_w8  [EMAX * 8];
__device__ int   g_idx8[EMAX * 8];
__device__ int   g_eord[EMAX];
__device__ int   g_rowptr[NMAX + 1];
__device__ int   g_cursor[NMAX];
__device__ int   g_degcnt[NMAX];
__device__ float g_red  [6 * CC];
__device__ float g_scale[3 * CC];
__device__ float g_shift[3 * CC];

// ---------------- helpers ----------------------------------------------------
__device__ __forceinline__ uint32_t smem_u32(const void* p) {
    uint32_t a;
    asm("{ .reg .u64 t; cvta.to.shared.u64 t, %1; cvt.u32.u64 %0, t; }" : "=r"(a) : "l"(p));
    return a;
}
__device__ __forceinline__ void cp_async16(uint32_t dst, const void* src, int vsize) {
    asm volatile("cp.async.cg.shared.global [%0], [%1], 16, %2;"
                 :: "r"(dst), "l"(src), "r"(vsize) : "memory");
}
#define CP_COMMIT() asm volatile("cp.async.commit_group;" ::: "memory")
#define CP_WAIT(n)  asm volatile("cp.async.wait_group %0;" :: "n"(n) : "memory")

__device__ __forceinline__ void ldsm4(uint32_t* r, uint32_t addr) {
    asm volatile("ldmatrix.sync.aligned.m8n8.x4.shared.b16 {%0,%1,%2,%3}, [%4];"
                 : "=r"(r[0]), "=r"(r[1]), "=r"(r[2]), "=r"(r[3]) : "r"(addr));
}
__device__ __forceinline__ void mma_f16(float* c, const uint32_t* a, uint32_t b0, uint32_t b1) {
    asm volatile("mma.sync.aligned.m16n8k16.row.col.f32.f16.f16.f32 "
                 "{%0,%1,%2,%3}, {%4,%5,%6,%7}, {%8,%9}, {%0,%1,%2,%3};"
                 : "+f"(c[0]), "+f"(c[1]), "+f"(c[2]), "+f"(c[3])
                 : "r"(a[0]), "r"(a[1]), "r"(a[2]), "r"(a[3]), "r"(b0), "r"(b1));
}

// ---------------- small kernels ---------------------------------------------
__global__ void k_zero(int n) {
    int i = blockIdx.x * blockDim.x + threadIdx.x;
    if (i < n) g_degcnt[i] = 0;
    if (i < 6 * CC) g_red[i] = 0.f;
}

__global__ void k_pre(const float* __restrict__ attr, const int* __restrict__ dst, int E) {
    int e = blockIdx.x * blockDim.x + threadIdx.x;
    if (e >= E) return;
    float v0 = attr[e * 3 + 0] * 4.f, v1 = attr[e * 3 + 1] * 4.f, v2 = attr[e * 3 + 2] * 4.f;
    float b0 = floorf(v0), b1 = floorf(v1), b2 = floorf(v2);
    float f0 = v0 - b0, f1 = v1 - b1, f2 = v2 - b2;
    int i0 = (int)b0, i1 = (int)b1, i2 = (int)b2;
#pragma unroll
    for (int m = 0; m < 8; m++) {
        int t0 = m & 1, t1 = (m >> 1) & 1, t2 = (m >> 2) & 1;
        float w = (t0 ? f0 : 1.f - f0) * (t1 ? f1 : 1.f - f1) * (t2 ? f2 : 1.f - f2);
        int c0 = min(max(i0 + t0, 0), 4);
        int c1 = min(max(i1 + t1, 0), 4);
        int c2 = min(max(i2 + t2, 0), 4);
        g_idx8[e * 8 + m] = (c0 * 5 + c1) * 5 + c2;
        g_w8[e * 8 + m] = w;
    }
    atomicAdd(&g_degcnt[dst[e]], 1);
}

__global__ void k_scan(int n) {
    __shared__ int sh[1024];
    __shared__ int carry;
    int t = threadIdx.x;
    if (t == 0) carry = 0;
    __syncthreads();
    for (int base = 0; base < n; base += 1024) {
        int i = base + t;
        int v = (i < n) ? g_degcnt[i] : 0;
        sh[t] = v;
        __syncthreads();
        for (int off = 1; off < 1024; off <<= 1) {
            int tv = (t >= off) ? sh[t - off] : 0;
            __syncthreads();
            sh[t] += tv;
            __syncthreads();
        }
        if (i < n) {
            int ex = carry + sh[t] - v;
            g_rowptr[i] = ex;
            g_cursor[i] = ex;
        }
        __syncthreads();
        if (t == 0) carry += sh[1023];
        __syncthreads();
    }
    if (t == 0) g_rowptr[n] = carry;
}

__global__ void k_fill(const int* __restrict__ dst, int E) {
    int e = blockIdx.x * blockDim.x + threadIdx.x;
    if (e >= E) return;
    int pos = atomicAdd(&g_cursor[dst[e]], 1);
    g_eord[pos] = e;
}

// ---------------- aggregation -----------------------------------------------
template <int CI, int WITH_S>
__global__ void k_agg(const float* __restrict__ X, const int* __restrict__ src, int ldacc) {
    extern __shared__ float acc[];
    int n = blockIdx.x;
    int c = threadIdx.x;
    float4 z4 = make_float4(0.f, 0.f, 0.f, 0.f);
    for (int i = c; i < KT * CI / 4; i += CI) ((float4*)acc)[i] = z4;
    int jb = g_rowptr[n], je = g_rowptr[n + 1];
    float invd = (je > jb) ? 1.f / (float)(je - jb) : 1.f;
    float ss = 0.f;
    __syncthreads();
    for (int j = jb; j < je; j++) {
        int e = g_eord[j];
        float xv = X[(size_t)src[e] * CI + c];
        if (WITH_S) ss += xv;
#pragma unroll
        for (int m = 0; m < 8; m++) {
            int ki = g_idx8[e * 8 + m];
            float w = g_w8[e * 8 + m];
            acc[ki * CI + c] += w * xv;
        }
    }
    __syncthreads();
    size_t base = (size_t)n * ldacc;
    __half2* hp = (__half2*)(g_acc + base);
    for (int i = c; i < KT * CI / 2; i += CI)
        hp[i] = __floats2half2_rn(acc[2 * i] * invd, acc[2 * i + 1] * invd);
    g_acc[base + KT * CI + c] = __float2half(X[(size_t)n * CI + c]);
    if (WITH_S) {
        g_sin[n * CC + c]       = __float2half(ss * invd);
        g_sin[n * CC + CI1 + c] = __float2half(X[n * CI1 + c]);
    }
}

// transpose weights into wt[n][k] (fp16)
__global__ void k_transp(const float* __restrict__ W, const float* __restrict__ Wr,
                         int Kmain, int Ktot, __half* __restrict__ wt) {
    int k = blockIdx.x * blockDim.x + threadIdx.x;
    int n = blockIdx.y;
    if (k >= Ktot) return;
    float v = (k < Kmain) ? W[(size_t)k * CC + n] : Wr[(size_t)(k - Kmain) * CC + n];
    wt[(size_t)n * Ktot + k] = __float2half(v);
}

// ---------------- fp16 mma.sync GEMM with ldmatrix feed -----------------------
// CTA 128x128, K-chunk 64 halves, 8 warps (warp tile 32x64), 3-stage cp.async.
// SMEM: stage = A(16KB)+B(16KB); rows of 128B = 8 chunks of 16B, chunk XOR (row&7).
// Split-K partials written non-atomically to P + blockIdx.y*pstride.
#define BK 64
#define NSTAGE 3
#define STG_BYTES 32768
#define TILE_BYTES 16384

__global__ __launch_bounds__(256, 2)
void k_mgemm(const __half* __restrict__ A, const __half* __restrict__ B, int ld,
             int M, float* __restrict__ P, int pstride, int chunks) {
    extern __shared__ char sm[];
    int tid = threadIdx.x, lane = tid & 31, wid = tid >> 5;
    int m0 = blockIdx.x * 128;
    int kb0 = blockIdx.y * chunks * BK;

    // producer mapping
    int pr_r = tid >> 1;
    int pr_h = (tid & 1) * 4;
    int grow = m0 + pr_r;
    int vA = (grow < M) ? 16 : 0;
    const __half* Abase = A + (size_t)grow * ld + kb0;
    const __half* Bbase = B + (size_t)pr_r * ld + kb0;

    const int warp_m0 = (wid & 3) * 32;
    const int warp_n0 = (wid >> 2) * 64;
    int g = lane >> 2, t = lane & 3;

    // ldmatrix per-lane address components
    uint32_t aoff[2]; int arx[2];
#pragma unroll
    for (int mf = 0; mf < 2; mf++) {
        int r = warp_m0 + mf * 16 + (lane & 15);
        aoff[mf] = r * 128; arx[mf] = r & 7;
    }
    int acb = lane >> 4;                 // 0/1: k-chunk half
    int grp = lane >> 3;
    int nf_half = grp >> 1, bcb = grp & 1;
    uint32_t boff[4]; int brx[4];
#pragma unroll
    for (int nfp = 0; nfp < 4; nfp++) {
        int r = warp_n0 + (nfp * 2 + nf_half) * 8 + (lane & 7);
        boff[nfp] = r * 128; brx[nfp] = r & 7;
    }

    float c[2][8][4];
#pragma unroll
    for (int i = 0; i < 2; i++)
#pragma unroll
        for (int j = 0; j < 8; j++)
#pragma unroll
            for (int q = 0; q < 4; q++) c[i][j][q] = 0.f;

    uint32_t smb = smem_u32(sm);

#define ISSUE(IT) do { \
    int _it = (IT); \
    if (_it < chunks) { \
        int _s = _it % NSTAGE; \
        uint32_t _dA = smb + _s * STG_BYTES + pr_r * 128; \
        uint32_t _dB = _dA + TILE_BYTES; \
        const __half* _sa = Abase + _it * BK; \
        const __half* _sb = Bbase + _it * BK; \
        _Pragma("unroll") \
        for (int _j = 0; _j < 4; _j++) { \
            int _c = pr_h + _j; \
            int _sc = _c ^ (pr_r & 7); \
            cp_async16(_dA + _sc * 16, _sa + _c * 8, vA); \
            cp_async16(_dB + _sc * 16, _sb + _c * 8, 16); \
        } \
    } \
    CP_COMMIT(); \
} while (0)

    ISSUE(0); ISSUE(1);

    for (int it = 0; it < chunks; it++) {
        CP_WAIT(1);
        __syncthreads();
        ISSUE(it + 2);
        uint32_t sA = smb + (it % NSTAGE) * STG_BYTES;
        uint32_t sB = sA + TILE_BYTES;
#pragma unroll
        for (int ks = 0; ks < 4; ks++) {
            int ca = ks * 2 + acb;
            uint32_t a[2][4];
            ldsm4(a[0], sA + aoff[0] + ((ca ^ arx[0]) << 4));
            ldsm4(a[1], sA + aoff[1] + ((ca ^ arx[1]) << 4));
            int cb = ks * 2 + bcb;
#pragma unroll
            for (int nfp = 0; nfp < 4; nfp++) {
                uint32_t bb[4];
                ldsm4(bb, sB + boff[nfp] + ((cb ^ brx[nfp]) << 4));
                mma_f16(c[0][2 * nfp],     a[0], bb[0], bb[1]);
                mma_f16(c[1][2 * nfp],     a[1], bb[0], bb[1]);
                mma_f16(c[0][2 * nfp + 1], a[0], bb[2], bb[3]);
                mma_f16(c[1][2 * nfp + 1], a[1], bb[2], bb[3]);
            }
        }
        __syncthreads();
    }
    CP_WAIT(0);

    float* Pp = P + (size_t)blockIdx.y * pstride;
#pragma unroll
    for (int mf = 0; mf < 2; mf++) {
        int r0 = m0 + warp_m0 + mf * 16 + g;
#pragma unroll
        for (int nf = 0; nf < 8; nf++) {
            int col = warp_n0 + nf * 8 + t * 2;
            if (r0 < M)
                *(float2*)&Pp[(size_t)r0 * CC + col] = make_float2(c[mf][nf][0], c[mf][nf][1]);
            if (r0 + 8 < M)
                *(float2*)&Pp[(size_t)(r0 + 8) * CC + col] = make_float2(c[mf][nf][2], c[mf][nf][3]);
        }
    }
#undef ISSUE
}

// ---------------- combine split-K partials + BN column sums -------------------
template <int SP>
__global__ void k_comb(const float* __restrict__ P, int pstride, int M,
                       float* __restrict__ out, float* __restrict__ red) {
    int c = threadIdx.x;
    float s = 0.f, s2 = 0.f;
    for (int r = blockIdx.x; r < M; r += gridDim.x) {
        size_t o = (size_t)r * CC + c;
        float v = P[o];
        if (SP > 1) v += P[pstride + o];
        if (SP > 2) v += P[2 * (size_t)pstride + o];
        out[o] = v;
        s += v; s2 += v * v;
    }
    atomicAdd(&red[c], s);
    atomicAdd(&red[CC + c], s2);
}

__global__ void k_stats(const float* __restrict__ red, const float* __restrict__ g,
                        const float* __restrict__ be, float* __restrict__ sc,
                        float* __restrict__ sh, int M) {
    int c = threadIdx.x;
    float mu = red[c] / (float)M;
    float var = red[CC + c] / (float)M - mu * mu;
    float s = g[c] * rsqrtf(var + 1e-5f);
    sc[c] = s;
    sh[c] = be[c] - mu * s;
}

__global__ void k_bnelu(const float* __restrict__ X, const float* __restrict__ sc,
                        const float* __restrict__ sh, float* __restrict__ Y, int n) {
    int i = blockIdx.x * blockDim.x + threadIdx.x;
    if (i >= n) return;
    int c = i & (CC - 1);
    float v = X[i] * sc[c] + sh[c];
    Y[i] = v > 0.f ? v : expm1f(v);
}

__global__ void k_final(const float* __restrict__ A, const float* __restrict__ B,
                        const float* __restrict__ sc2, const float* __restrict__ sh2,
                        const float* __restrict__ scS, const float* __restrict__ shS,
                        float* __restrict__ out, int n) {
    int i = blockIdx.x * blockDim.x + threadIdx.x;
    if (i >= n) return;
    int c = i & (CC - 1);
    float v = A[i] * sc2[c] + sh2[c] + B[i] * scS[c] + shS[c];
    out[i] = v > 0.f ? v : expm1f(v);
}

// ---------------- launch ----------------------------------------------------
extern "C" void kernel_launch(void* const* d_in, const int* in_sizes, int n_in,
                              void* d_out, int out_size) {
    const float* x    = (const float*)d_in[0];
    const int*   ei   = (const int*)d_in[1];
    const float* attr = (const float*)d_in[2];
    const float* W1   = (const float*)d_in[3];
    const float* Wr1  = (const float*)d_in[4];
    const float* g1   = (const float*)d_in[6];
    const float* be1  = (const float*)d_in[7];
    const float* W2   = (const float*)d_in[8];
    const float* Wr2  = (const float*)d_in[9];
    const float* g2   = (const float*)d_in[11];
    const float* be2  = (const float*)d_in[12];
    const float* Wsc  = (const float*)d_in[13];
    const float* Wrsc = (const float*)d_in[14];
    const float* gsc  = (const float*)d_in[16];
    const float* besc = (const float*)d_in[17];
    // bias inputs b1/b2/bsc dropped: constant column shifts cancel in train-mode BN

    int E = in_sizes[1] / 2;
    int M = in_sizes[0] / CI1;
    const int* src = ei;
    const int* dst = ei + E;

    __half *acc, *wt, *sinb;
    float *part, *out1, *h1e, *out2, *outs, *red, *scale, *shift;
    cudaGetSymbolAddress((void**)&acc,   g_acc);
    cudaGetSymbolAddress((void**)&wt,    g_wt);
    cudaGetSymbolAddress((void**)&sinb,  g_sin);
    cudaGetSymbolAddress((void**)&part,  g_part);
    cudaGetSymbolAddress((void**)&out1,  g_out1);
    cudaGetSymbolAddress((void**)&h1e,   g_h1e);
    cudaGetSymbolAddress((void**)&out2,  g_out2);
    cudaGetSymbolAddress((void**)&outs,  g_outs);
    cudaGetSymbolAddress((void**)&red,   g_red);
    cudaGetSymbolAddress((void**)&scale, g_scale);
    cudaGetSymbolAddress((void**)&shift, g_shift);

    cudaFuncSetAttribute(k_agg<CC, 0>, cudaFuncAttributeMaxDynamicSharedMemorySize, KT * CC * 4);
    int dsm = NSTAGE * STG_BYTES;   // 96KB
    cudaFuncSetAttribute(k_mgemm, cudaFuncAttributeMaxDynamicSharedMemorySize, dsm);

    int eb = (E + 255) / 256;
    int mtiles = (M + 127) / 128;
    int pstride = M * CC;

    // CSR build + spline basis
    k_zero<<<(M + 255) / 256, 256>>>(M);
    k_pre<<<eb, 256>>>(attr, dst, E);
    k_scan<<<1, 1024>>>(M);
    k_fill<<<eb, 256>>>(dst, E);

    // conv1: aggregate (+fused shortcut agg), transpose weights, GEMM (splitK=3)
    k_agg<CI1, 1><<<M, CI1, KT * CI1 * 4>>>(x, src, LD1);
    k_transp<<<dim3((LD1 + 255) / 256, CC), 256>>>(W1, Wr1, KT * CI1, LD1, wt);
    k_mgemm<<<dim3(mtiles, 3), 256, dsm>>>(acc, wt, LD1, M, part, pstride, (LD1 / BK) / 3);
    k_comb<3><<<256, CC>>>(part, pstride, M, out1, red);
    k_stats<<<1, CC>>>(red, g1, be1, scale, shift, M);
    k_bnelu<<<(M * CC + 255) / 256, 256>>>(out1, scale, shift, h1e, M * CC);

    // conv2 (splitK=3)
    k_agg<CC, 0><<<M, CC, KT * CC * 4>>>(h1e, src, LD2);
    k_transp<<<dim3((LD2 + 255) / 256, CC), 256>>>(W2, Wr2, KT * CC, LD2, wt);
    k_mgemm<<<dim3(mtiles, 3), 256, dsm>>>(acc, wt, LD2, M, part, pstride, (LD2 / BK) / 3);
    k_comb<3><<<256, CC>>>(part, pstride, M, out2, red + 2 * CC);
    k_stats<<<1, CC>>>(red + 2 * CC, g2, be2, scale + CC, shift + CC, M);

    // shortcut: [mean_agg | x] @ [Wsc ; Wrsc]
    k_transp<<<dim3((CC + 255) / 256, CC), 256>>>(Wsc, Wrsc, CI1, CC, wt);
    k_mgemm<<<dim3(mtiles, 1), 256, dsm>>>(sinb, wt, CC, M, part, pstride, CC / BK);
    k_comb<1><<<256, CC>>>(part, pstride, M, outs, red + 4 * CC);
    k_stats<<<1, CC>>>(red + 4 * CC, gsc, besc, scale + 2 * CC, shift + 2 * CC, M);

    // final elu(bn2(h) + bnsc(s))
    k_final<<<(M * CC + 255) / 256, 256>>>(out2, outs, scale + CC, shift + CC,
                                           scale + 2 * CC, shift + 2 * CC,
                                           (float*)d_out, M * CC);
}

// round 9
// speedup vs baseline: 4.0550x; 1.0959x over previous
#include <cuda_runtime.h>
#include <cuda_fp16.h>
#include <math.h>
#include <stdint.h>

#define NMAX 10000
#define EMAX 160000
#define KT   125
#define CI1  64
#define CC   128
#define LD1  (KT*CI1 + CI1)    // 8064
#define LD2  (KT*CC + CC)      // 16128

// ---------------- scratch (device globals: no allocations allowed) ----------
__device__ __align__(1024) __half g_acc[(size_t)NMAX * LD2];  // 322MB
__device__ __align__(1024) __half g_wt [CC * LD2];            // transposed weights [n][k]
__device__ __align__(1024) __half g_sin[NMAX * CC];           // [s_agg | x] shortcut A
__device__ __align__(1024) float g_part[3 * (size_t)NMAX * CC]; // split-K partials
__device__ __align__(1024) float g_out1[NMAX * CC];
__device__ __align__(1024) float g_h1e [NMAX * CC];
__device__ __align__(1024) float g_out2[NMAX * CC];
__device__ __align__(1024) float g_outs[NMAX * CC];
__device__ __align__(16) float g_w8  [EMAX * 8];   // CSR-ordered basis weights
__device__ __align__(16) int   g_idx8[EMAX * 8];   // CSR-ordered kernel indices
__device__ int   g_srco[EMAX];                     // CSR-ordered source node
__device__ int   g_rowptr[NMAX + 1];
__device__ int   g_cursor[NMAX];
__device__ int   g_degcnt[NMAX];
__device__ float g_red  [6 * CC];
__device__ float g_scale[3 * CC];
__device__ float g_shift[3 * CC];

// ---------------- helpers ----------------------------------------------------
__device__ __forceinline__ uint32_t smem_u32(const void* p) {
    uint32_t a;
    asm("{ .reg .u64 t; cvta.to.shared.u64 t, %1; cvt.u32.u64 %0, t; }" : "=r"(a) : "l"(p));
    return a;
}
__device__ __forceinline__ void cp_async16(uint32_t dst, const void* src, int vsize) {
    asm volatile("cp.async.cg.shared.global [%0], [%1], 16, %2;"
                 :: "r"(dst), "l"(src), "r"(vsize) : "memory");
}
#define CP_COMMIT() asm volatile("cp.async.commit_group;" ::: "memory")
#define CP_WAIT(n)  asm volatile("cp.async.wait_group %0;" :: "n"(n) : "memory")

__device__ __forceinline__ void ldsm4(uint32_t* r, uint32_t addr) {
    asm volatile("ldmatrix.sync.aligned.m8n8.x4.shared.b16 {%0,%1,%2,%3}, [%4];"
                 : "=r"(r[0]), "=r"(r[1]), "=r"(r[2]), "=r"(r[3]) : "r"(addr));
}
__device__ __forceinline__ void mma_f16(float* c, const uint32_t* a, uint32_t b0, uint32_t b1) {
    asm volatile("mma.sync.aligned.m16n8k16.row.col.f32.f16.f16.f32 "
                 "{%0,%1,%2,%3}, {%4,%5,%6,%7}, {%8,%9}, {%0,%1,%2,%3};"
                 : "+f"(c[0]), "+f"(c[1]), "+f"(c[2]), "+f"(c[3])
                 : "r"(a[0]), "r"(a[1]), "r"(a[2]), "r"(a[3]), "r"(b0), "r"(b1));
}

// ---------------- small kernels ---------------------------------------------
__global__ void k_zero(int n) {
    int i = blockIdx.x * blockDim.x + threadIdx.x;
    if (i < n) g_degcnt[i] = 0;
    if (i < 6 * CC) g_red[i] = 0.f;
}

// degree count only
__global__ void k_pre(const int* __restrict__ dst, int E) {
    int e = blockIdx.x * blockDim.x + threadIdx.x;
    if (e < E) atomicAdd(&g_degcnt[dst[e]], 1);
}

__global__ void k_scan(int n) {
    __shared__ int sh[1024];
    __shared__ int carry;
    int t = threadIdx.x;
    if (t == 0) carry = 0;
    __syncthreads();
    for (int base = 0; base < n; base += 1024) {
        int i = base + t;
        int v = (i < n) ? g_degcnt[i] : 0;
        sh[t] = v;
        __syncthreads();
        for (int off = 1; off < 1024; off <<= 1) {
            int tv = (t >= off) ? sh[t - off] : 0;
            __syncthreads();
            sh[t] += tv;
            __syncthreads();
        }
        if (i < n) {
            int ex = carry + sh[t] - v;
            g_rowptr[i] = ex;
            g_cursor[i] = ex;
        }
        __syncthreads();
        if (t == 0) carry += sh[1023];
        __syncthreads();
    }
    if (t == 0) g_rowptr[n] = carry;
}

// CSR fill: slot by atomic cursor, spline basis computed and stored IN CSR ORDER
__global__ void k_fill(const float* __restrict__ attr, const int* __restrict__ src,
                       const int* __restrict__ dst, int E) {
    int e = blockIdx.x * blockDim.x + threadIdx.x;
    if (e >= E) return;
    int pos = atomicAdd(&g_cursor[dst[e]], 1);
    g_srco[pos] = src[e];
    float v0 = attr[e * 3 + 0] * 4.f, v1 = attr[e * 3 + 1] * 4.f, v2 = attr[e * 3 + 2] * 4.f;
    float b0 = floorf(v0), b1 = floorf(v1), b2 = floorf(v2);
    float f0 = v0 - b0, f1 = v1 - b1, f2 = v2 - b2;
    int i0 = (int)b0, i1 = (int)b1, i2 = (int)b2;
#pragma unroll
    for (int m = 0; m < 8; m++) {
        int t0 = m & 1, t1 = (m >> 1) & 1, t2 = (m >> 2) & 1;
        float w = (t0 ? f0 : 1.f - f0) * (t1 ? f1 : 1.f - f1) * (t2 ? f2 : 1.f - f2);
        int c0 = min(max(i0 + t0, 0), 4);
        int c1 = min(max(i1 + t1, 0), 4);
        int c2 = min(max(i2 + t2, 0), 4);
        g_idx8[pos * 8 + m] = (c0 * 5 + c1) * 5 + c2;
        g_w8[pos * 8 + m] = w;
    }
}

// ---------------- aggregation: linear CSR reads, pipelined x prefetch --------
template <int CI, int WITH_S>
__global__ void k_agg(const float* __restrict__ X, int ldacc) {
    extern __shared__ float acc[];
    int n = blockIdx.x;
    int c = threadIdx.x;
    float4 z4 = make_float4(0.f, 0.f, 0.f, 0.f);
    for (int i = c; i < KT * CI / 4; i += CI) ((float4*)acc)[i] = z4;
    int jb = g_rowptr[n], je = g_rowptr[n + 1];
    float invd = (je > jb) ? 1.f / (float)(je - jb) : 1.f;
    float ss = 0.f;
    __syncthreads();
    float xv = 0.f;
    if (jb < je) xv = X[(size_t)g_srco[jb] * CI + c];
    for (int j = jb; j < je; j++) {
        float xc = xv;
        if (j + 1 < je) xv = X[(size_t)g_srco[j + 1] * CI + c];   // prefetch next row
        if (WITH_S) ss += xc;
#pragma unroll
        for (int m = 0; m < 8; m++) {
            int ki = g_idx8[j * 8 + m];
            float w = g_w8[j * 8 + m];
            acc[ki * CI + c] += w * xc;
        }
    }
    __syncthreads();
    size_t base = (size_t)n * ldacc;
    __half2* hp = (__half2*)(g_acc + base);
    for (int i = c; i < KT * CI / 2; i += CI)
        hp[i] = __floats2half2_rn(acc[2 * i] * invd, acc[2 * i + 1] * invd);
    g_acc[base + KT * CI + c] = __float2half(X[(size_t)n * CI + c]);
    if (WITH_S) {
        g_sin[n * CC + c]       = __float2half(ss * invd);
        g_sin[n * CC + CI1 + c] = __float2half(X[n * CI1 + c]);
    }
}

// tiled transpose: W[k][n] (+Wr appended) -> wt[n][k] fp16, fully coalesced
__global__ void k_transp(const float* __restrict__ W, const float* __restrict__ Wr,
                         int Kmain, int Ktot, __half* __restrict__ wt) {
    __shared__ float tile[32][33];
    int kb = blockIdx.x * 32, nb = blockIdx.y * 32;
    int tx = threadIdx.x, ty = threadIdx.y;
#pragma unroll
    for (int i = 0; i < 32; i += 8) {
        int k = kb + ty + i;
        const float* srcp = (k < Kmain) ? &W[(size_t)k * CC] : &Wr[(size_t)(k - Kmain) * CC];
        tile[ty + i][tx] = srcp[nb + tx];
    }
    __syncthreads();
#pragma unroll
    for (int i = 0; i < 32; i += 8) {
        int nn = nb + ty + i;
        wt[(size_t)nn * Ktot + kb + tx] = __float2half(tile[tx][ty + i]);
    }
}

// ---------------- fp16 mma.sync GEMM with ldmatrix feed -----------------------
#define BK 64
#define NSTAGE 3
#define STG_BYTES 32768
#define TILE_BYTES 16384

__global__ __launch_bounds__(256, 2)
void k_mgemm(const __half* __restrict__ A, const __half* __restrict__ B, int ld,
             int M, float* __restrict__ P, int pstride, int chunks) {
    extern __shared__ char sm[];
    int tid = threadIdx.x, lane = tid & 31, wid = tid >> 5;
    int m0 = blockIdx.x * 128;
    int kb0 = blockIdx.y * chunks * BK;

    int pr_r = tid >> 1;
    int pr_h = (tid & 1) * 4;
    int grow = m0 + pr_r;
    int vA = (grow < M) ? 16 : 0;
    const __half* Abase = A + (size_t)grow * ld + kb0;
    const __half* Bbase = B + (size_t)pr_r * ld + kb0;

    const int warp_m0 = (wid & 3) * 32;
    const int warp_n0 = (wid >> 2) * 64;
    int g = lane >> 2, t = lane & 3;

    uint32_t aoff[2]; int arx[2];
#pragma unroll
    for (int mf = 0; mf < 2; mf++) {
        int r = warp_m0 + mf * 16 + (lane & 15);
        aoff[mf] = r * 128; arx[mf] = r & 7;
    }
    int acb = lane >> 4;
    int grp = lane >> 3;
    int nf_half = grp >> 1, bcb = grp & 1;
    uint32_t boff[4]; int brx[4];
#pragma unroll
    for (int nfp = 0; nfp < 4; nfp++) {
        int r = warp_n0 + (nfp * 2 + nf_half) * 8 + (lane & 7);
        boff[nfp] = r * 128; brx[nfp] = r & 7;
    }

    float c[2][8][4];
#pragma unroll
    for (int i = 0; i < 2; i++)
#pragma unroll
        for (int j = 0; j < 8; j++)
#pragma unroll
            for (int q = 0; q < 4; q++) c[i][j][q] = 0.f;

    uint32_t smb = smem_u32(sm);

#define ISSUE(IT) do { \
    int _it = (IT); \
    if (_it < chunks) { \
        int _s = _it % NSTAGE; \
        uint32_t _dA = smb + _s * STG_BYTES + pr_r * 128; \
        uint32_t _dB = _dA + TILE_BYTES; \
        const __half* _sa = Abase + _it * BK; \
        const __half* _sb = Bbase + _it * BK; \
        _Pragma("unroll") \
        for (int _j = 0; _j < 4; _j++) { \
            int _c = pr_h + _j; \
            int _sc = _c ^ (pr_r & 7); \
            cp_async16(_dA + _sc * 16, _sa + _c * 8, vA); \
            cp_async16(_dB + _sc * 16, _sb + _c * 8, 16); \
        } \
    } \
    CP_COMMIT(); \
} while (0)

    ISSUE(0); ISSUE(1);

    for (int it = 0; it < chunks; it++) {
        CP_WAIT(1);
        __syncthreads();
        ISSUE(it + 2);
        uint32_t sA = smb + (it % NSTAGE) * STG_BYTES;
        uint32_t sB = sA + TILE_BYTES;
#pragma unroll
        for (int ks = 0; ks < 4; ks++) {
            int ca = ks * 2 + acb;
            uint32_t a[2][4];
            ldsm4(a[0], sA + aoff[0] + ((ca ^ arx[0]) << 4));
            ldsm4(a[1], sA + aoff[1] + ((ca ^ arx[1]) << 4));
            int cb = ks * 2 + bcb;
#pragma unroll
            for (int nfp = 0; nfp < 4; nfp++) {
                uint32_t bb[4];
                ldsm4(bb, sB + boff[nfp] + ((cb ^ brx[nfp]) << 4));
                mma_f16(c[0][2 * nfp],     a[0], bb[0], bb[1]);
                mma_f16(c[1][2 * nfp],     a[1], bb[0], bb[1]);
                mma_f16(c[0][2 * nfp + 1], a[0], bb[2], bb[3]);
                mma_f16(c[1][2 * nfp + 1], a[1], bb[2], bb[3]);
            }
        }
        __syncthreads();
    }
    CP_WAIT(0);

    float* Pp = P + (size_t)blockIdx.y * pstride;
#pragma unroll
    for (int mf = 0; mf < 2; mf++) {
        int r0 = m0 + warp_m0 + mf * 16 + g;
#pragma unroll
        for (int nf = 0; nf < 8; nf++) {
            int col = warp_n0 + nf * 8 + t * 2;
            if (r0 < M)
                *(float2*)&Pp[(size_t)r0 * CC + col] = make_float2(c[mf][nf][0], c[mf][nf][1]);
            if (r0 + 8 < M)
                *(float2*)&Pp[(size_t)(r0 + 8) * CC + col] = make_float2(c[mf][nf][2], c[mf][nf][3]);
        }
    }
#undef ISSUE
}

// ---------------- combine split-K partials + BN column sums -------------------
template <int SP>
__global__ void k_comb(const float* __restrict__ P, int pstride, int M,
                       float* __restrict__ out, float* __restrict__ red) {
    int c = threadIdx.x;
    float s = 0.f, s2 = 0.f;
    for (int r = blockIdx.x; r < M; r += gridDim.x) {
        size_t o = (size_t)r * CC + c;
        float v = P[o];
        if (SP > 1) v += P[pstride + o];
        if (SP > 2) v += P[2 * (size_t)pstride + o];
        out[o] = v;
        s += v; s2 += v * v;
    }
    atomicAdd(&red[c], s);
    atomicAdd(&red[CC + c], s2);
}

__global__ void k_stats(const float* __restrict__ red, const float* __restrict__ g,
                        const float* __restrict__ be, float* __restrict__ sc,
                        float* __restrict__ sh, int M) {
    int c = threadIdx.x;
    float mu = red[c] / (float)M;
    float var = red[CC + c] / (float)M - mu * mu;
    float s = g[c] * rsqrtf(var + 1e-5f);
    sc[c] = s;
    sh[c] = be[c] - mu * s;
}

__global__ void k_bnelu(const float* __restrict__ X, const float* __restrict__ sc,
                        const float* __restrict__ sh, float* __restrict__ Y, int n) {
    int i = blockIdx.x * blockDim.x + threadIdx.x;
    if (i >= n) return;
    int c = i & (CC - 1);
    float v = X[i] * sc[c] + sh[c];
    Y[i] = v > 0.f ? v : expm1f(v);
}

__global__ void k_final(const float* __restrict__ A, const float* __restrict__ B,
                        const float* __restrict__ sc2, const float* __restrict__ sh2,
                        const float* __restrict__ scS, const float* __restrict__ shS,
                        float* __restrict__ out, int n) {
    int i = blockIdx.x * blockDim.x + threadIdx.x;
    if (i >= n) return;
    int c = i & (CC - 1);
    float v = A[i] * sc2[c] + sh2[c] + B[i] * scS[c] + shS[c];
    out[i] = v > 0.f ? v : expm1f(v);
}

// ---------------- launch ----------------------------------------------------
extern "C" void kernel_launch(void* const* d_in, const int* in_sizes, int n_in,
                              void* d_out, int out_size) {
    const float* x    = (const float*)d_in[0];
    const int*   ei   = (const int*)d_in[1];
    const float* attr = (const float*)d_in[2];
    const float* W1   = (const float*)d_in[3];
    const float* Wr1  = (const float*)d_in[4];
    const float* g1   = (const float*)d_in[6];
    const float* be1  = (const float*)d_in[7];
    const float* W2   = (const float*)d_in[8];
    const float* Wr2  = (const float*)d_in[9];
    const float* g2   = (const float*)d_in[11];
    const float* be2  = (const float*)d_in[12];
    const float* Wsc  = (const float*)d_in[13];
    const float* Wrsc = (const float*)d_in[14];
    const float* gsc  = (const float*)d_in[16];
    const float* besc = (const float*)d_in[17];
    // bias inputs b1/b2/bsc dropped: constant column shifts cancel in train-mode BN

    int E = in_sizes[1] / 2;
    int M = in_sizes[0] / CI1;
    const int* src = ei;
    const int* dst = ei + E;

    __half *acc, *wt, *sinb;
    float *part, *out1, *h1e, *out2, *outs, *red, *scale, *shift;
    cudaGetSymbolAddress((void**)&acc,   g_acc);
    cudaGetSymbolAddress((void**)&wt,    g_wt);
    cudaGetSymbolAddress((void**)&sinb,  g_sin);
    cudaGetSymbolAddress((void**)&part,  g_part);
    cudaGetSymbolAddress((void**)&out1,  g_out1);
    cudaGetSymbolAddress((void**)&h1e,   g_h1e);
    cudaGetSymbolAddress((void**)&out2,  g_out2);
    cudaGetSymbolAddress((void**)&outs,  g_outs);
    cudaGetSymbolAddress((void**)&red,   g_red);
    cudaGetSymbolAddress((void**)&scale, g_scale);
    cudaGetSymbolAddress((void**)&shift, g_shift);

    cudaFuncSetAttribute(k_agg<CC, 0>, cudaFuncAttributeMaxDynamicSharedMemorySize, KT * CC * 4);
    int dsm = NSTAGE * STG_BYTES;   // 96KB
    cudaFuncSetAttribute(k_mgemm, cudaFuncAttributeMaxDynamicSharedMemorySize, dsm);

    int eb = (E + 255) / 256;
    int mtiles = (M + 127) / 128;
    int pstride = M * CC;

    // CSR build (basis computed in k_fill, stored CSR-ordered)
    k_zero<<<(M + 255) / 256, 256>>>(M);
    k_pre<<<eb, 256>>>(dst, E);
    k_scan<<<1, 1024>>>(M);
    k_fill<<<eb, 256>>>(attr, src, dst, E);

    // conv1: aggregate (+fused shortcut agg), transpose weights, GEMM (splitK=3)
    k_agg<CI1, 1><<<M, CI1, KT * CI1 * 4>>>(x, LD1);
    k_transp<<<dim3(LD1 / 32, CC / 32), dim3(32, 8)>>>(W1, Wr1, KT * CI1, LD1, wt);
    k_mgemm<<<dim3(mtiles, 3), 256, dsm>>>(acc, wt, LD1, M, part, pstride, (LD1 / BK) / 3);
    k_comb<3><<<256, CC>>>(part, pstride, M, out1, red);
    k_stats<<<1, CC>>>(red, g1, be1, scale, shift, M);
    k_bnelu<<<(M * CC + 255) / 256, 256>>>(out1, scale, shift, h1e, M * CC);

    // conv2 (splitK=3)
    k_agg<CC, 0><<<M, CC, KT * CC * 4>>>(h1e, LD2);
    k_transp<<<dim3(LD2 / 32, CC / 32), dim3(32, 8)>>>(W2, Wr2, KT * CC, LD2, wt);
    k_mgemm<<<dim3(mtiles, 3), 256, dsm>>>(acc, wt, LD2, M, part, pstride, (LD2 / BK) / 3);
    k_comb<3><<<256, CC>>>(part, pstride, M, out2, red + 2 * CC);
    k_stats<<<1, CC>>>(red + 2 * CC, g2, be2, scale + CC, shift + CC, M);

    // shortcut: [mean_agg | x] @ [Wsc ; Wrsc]
    k_transp<<<dim3(CC / 32, CC / 32), dim3(32, 8)>>>(Wsc, Wrsc, CI1, CC, wt);
    k_mgemm<<<dim3(mtiles, 1), 256, dsm>>>(sinb, wt, CC, M, part, pstride, CC / BK);
    k_comb<1><<<256, CC>>>(part, pstride, M, outs, red + 4 * CC);
    k_stats<<<1, CC>>>(red + 4 * CC, gsc, besc, scale + 2 * CC, shift + 2 * CC, M);

    // final elu(bn2(h) + bnsc(s))
    k_final<<<(M * CC + 255) / 256, 256>>>(out2, outs, scale + CC, shift + CC,
                                           scale + 2 * CC, shift + 2 * CC,
                                           (float*)d_out, M * CC);
}